// round 1
// baseline (speedup 1.0000x reference)
#include <cuda_runtime.h>
#include <math.h>

#define BATCH 4
#define SEQ   2048
#define EMB   1024
#define HEADS 16
#define HDIM  64
#define MROWS (BATCH*SEQ)          // 8192
#define SCALE 0.125f               // 64^-0.5

// ---------------- scratch (static device allocations are allowed) ----------
static __device__ float g_q[(size_t)MROWS * EMB];   // [B,H,N,D]
static __device__ float g_k[(size_t)MROWS * EMB];   // [B,H,N,D]
static __device__ float g_v[(size_t)MROWS * EMB];   // [B,H,N,D]
static __device__ float g_ctx[(size_t)MROWS * EMB]; // [B,N,C]

// ---------------- tiled SGEMM: out = A(MxK) @ W(KxN') + bias ---------------
// BM=128, BN=128, BK=8, 256 threads, 8x8 per-thread microtile.
// BHND_OUT: scatter output element (m,c) into [B,H,N,D] layout.
template <bool BHND_OUT>
__global__ __launch_bounds__(256)
void gemm_bias_kernel(const float* __restrict__ A,
                      const float* __restrict__ W,
                      const float* __restrict__ bias,
                      float* __restrict__ out)
{
    const int BM = 128, BN = 128, BK = 8, TM = 8, TN = 8;
    __shared__ float As[BK][BM];
    __shared__ float Bs[BK][BN];

    const int bm  = blockIdx.y;
    const int bn  = blockIdx.x;
    const int tid = threadIdx.x;

    const int loadArow = tid >> 1;         // 0..127
    const int loadAcol = (tid & 1) * 4;    // 0 or 4
    const int loadBrow = tid >> 5;         // 0..7
    const int loadBcol = (tid & 31) * 4;   // 0..124

    const int tr = (tid >> 4) * TM;        // 0..120
    const int tc = (tid & 15) * TN;        // 0..120

    float acc[TM][TN];
#pragma unroll
    for (int i = 0; i < TM; i++)
#pragma unroll
        for (int j = 0; j < TN; j++) acc[i][j] = 0.f;

    const float* Aptr = A + (size_t)(bm * BM) * EMB;
    const float* Wptr = W + bn * BN;

    for (int k0 = 0; k0 < EMB; k0 += BK) {
        float4 a4 = *(const float4*)(Aptr + (size_t)loadArow * EMB + k0 + loadAcol);
        As[loadAcol + 0][loadArow] = a4.x;
        As[loadAcol + 1][loadArow] = a4.y;
        As[loadAcol + 2][loadArow] = a4.z;
        As[loadAcol + 3][loadArow] = a4.w;
        float4 b4 = *(const float4*)(Wptr + (size_t)(k0 + loadBrow) * EMB + loadBcol);
        *(float4*)&Bs[loadBrow][loadBcol] = b4;
        __syncthreads();

#pragma unroll
        for (int k = 0; k < BK; k++) {
            float ar[TM], br[TN];
            *(float4*)&ar[0] = *(const float4*)&As[k][tr];
            *(float4*)&ar[4] = *(const float4*)&As[k][tr + 4];
            *(float4*)&br[0] = *(const float4*)&Bs[k][tc];
            *(float4*)&br[4] = *(const float4*)&Bs[k][tc + 4];
#pragma unroll
            for (int i = 0; i < TM; i++)
#pragma unroll
                for (int j = 0; j < TN; j++)
                    acc[i][j] = fmaf(ar[i], br[j], acc[i][j]);
        }
        __syncthreads();
    }

#pragma unroll
    for (int i = 0; i < TM; i++) {
        const int m = bm * BM + tr + i;
#pragma unroll
        for (int j = 0; j < TN; j++) {
            const int c = bn * BN + tc + j;
            const float vv = acc[i][j] + bias[c];
            if (BHND_OUT) {
                const int b = m >> 11, n = m & 2047;
                const int h = c >> 6,  d = c & 63;
                out[((((size_t)b * HEADS + h) * SEQ + n) << 6) + d] = vv;
            } else {
                out[(size_t)m * EMB + c] = vv;
            }
        }
    }
}

// ---------------- flash attention (fp32, online softmax) -------------------
// grid = (SEQ/64, BATCH*HEADS), 256 threads.
// Thread t handles S/O row r = t/4, 16 columns starting at (t%3)*16.
#define BQ 64
#define BKV 64
#define LDP 65   // padded row stride for Qs/Kt/Ss

__global__ __launch_bounds__(256)
void attn_kernel(const float* __restrict__ q,
                 const float* __restrict__ k,
                 const float* __restrict__ v,
                 float* __restrict__ ctx)
{
    extern __shared__ float smem[];
    float* Qs = smem;                 // BQ  x LDP (scaled Q)
    float* Kt = Qs + BQ * LDP;        // HDIM x LDP (K transposed)
    float* Ss = Kt + HDIM * LDP;      // BQ  x LDP (P tile)
    float* Vs = Ss + BQ * LDP;        // BKV x HDIM

    const int bh  = blockIdx.y;       // 0..63  (b*16+h)
    const int qt  = blockIdx.x;       // 0..31
    const int tid = threadIdx.x;

    const float* qb = q + ((size_t)bh * SEQ + qt * BQ) * HDIM;
    const float* kb = k + (size_t)bh * SEQ * HDIM;
    const float* vb = v + (size_t)bh * SEQ * HDIM;

    // load + scale Q tile (64x64)
    for (int i = tid; i < BQ * HDIM / 4; i += 256) {
        const int row = i >> 4;
        const int col = (i & 15) * 4;
        float4 t = ((const float4*)(qb + (size_t)row * HDIM))[i & 15];
        Qs[row * LDP + col + 0] = t.x * SCALE;
        Qs[row * LDP + col + 1] = t.y * SCALE;
        Qs[row * LDP + col + 2] = t.z * SCALE;
        Qs[row * LDP + col + 3] = t.w * SCALE;
    }

    const int r  = tid >> 2;          // 0..63
    const int c0 = (tid & 3) * 16;    // 0,16,32,48

    float m_i = -INFINITY, l_i = 0.f;
    float o[16];
#pragma unroll
    for (int i = 0; i < 16; i++) o[i] = 0.f;

    for (int j = 0; j < SEQ / BKV; j++) {
        __syncthreads();   // previous PV done (Vs/Ss free), Qs ready on iter 0

        // load K tile transposed (padded) + V tile
        for (int i = tid; i < BKV * HDIM / 4; i += 256) {
            const int row  = i >> 4;
            const int col4 = (i & 15) * 4;
            float4 tk = ((const float4*)(kb + (size_t)(j * BKV + row) * HDIM))[i & 15];
            Kt[(col4 + 0) * LDP + row] = tk.x;
            Kt[(col4 + 1) * LDP + row] = tk.y;
            Kt[(col4 + 2) * LDP + row] = tk.z;
            Kt[(col4 + 3) * LDP + row] = tk.w;
            float4 tv = ((const float4*)(vb + (size_t)(j * BKV + row) * HDIM))[i & 15];
            *(float4*)&Vs[row * HDIM + col4] = tv;
        }
        __syncthreads();

        // S = Qs @ K^T  (16 cols per thread)
        float s[16];
#pragma unroll
        for (int cc = 0; cc < 16; cc++) s[cc] = 0.f;
#pragma unroll 4
        for (int kk = 0; kk < HDIM; kk++) {
            const float qv = Qs[r * LDP + kk];
            const float* kp = &Kt[kk * LDP + c0];
#pragma unroll
            for (int cc = 0; cc < 16; cc++)
                s[cc] = fmaf(qv, kp[cc], s[cc]);
        }

        // online softmax (4 lanes per row cooperate via shuffles)
        float mt = s[0];
#pragma unroll
        for (int cc = 1; cc < 16; cc++) mt = fmaxf(mt, s[cc]);
        mt = fmaxf(mt, __shfl_xor_sync(0xffffffffu, mt, 1));
        mt = fmaxf(mt, __shfl_xor_sync(0xffffffffu, mt, 2));
        const float m_new = fmaxf(m_i, mt);
        const float corr  = __expf(m_i - m_new);
        float psum = 0.f;
#pragma unroll
        for (int cc = 0; cc < 16; cc++) {
            const float p = __expf(s[cc] - m_new);
            s[cc] = p;
            psum += p;
        }
        psum += __shfl_xor_sync(0xffffffffu, psum, 1);
        psum += __shfl_xor_sync(0xffffffffu, psum, 2);
        l_i = l_i * corr + psum;
        m_i = m_new;
#pragma unroll
        for (int cc = 0; cc < 16; cc++) o[cc] *= corr;

        // stage P
#pragma unroll
        for (int cc = 0; cc < 16; cc++) Ss[r * LDP + c0 + cc] = s[cc];
        __syncthreads();

        // O += P @ V
#pragma unroll 4
        for (int kk = 0; kk < BKV; kk++) {
            const float p = Ss[r * LDP + kk];
            const float* vp = &Vs[kk * HDIM + c0];
#pragma unroll
            for (int cc = 0; cc < 16; cc++)
                o[cc] = fmaf(p, vp[cc], o[cc]);
        }
    }

    // write context in [B,N,C] layout
    const float inv = 1.f / l_i;
    const int b = bh >> 4, h = bh & 15;
    const int n = qt * BQ + r;
    float* op = ctx + ((size_t)b * SEQ + n) * EMB + h * HDIM + c0;
#pragma unroll
    for (int cc = 0; cc < 16; cc++) op[cc] = o[cc] * inv;
}

// ---------------------------------------------------------------------------
extern "C" void kernel_launch(void* const* d_in, const int* in_sizes, int n_in,
                              void* d_out, int out_size)
{
    const float* x   = (const float*)d_in[0];
    const float* w_q = (const float*)d_in[1];
    const float* b_q = (const float*)d_in[2];
    const float* w_k = (const float*)d_in[3];
    const float* b_k = (const float*)d_in[4];
    const float* w_v = (const float*)d_in[5];
    const float* b_v = (const float*)d_in[6];
    const float* w_o = (const float*)d_in[7];
    const float* b_o = (const float*)d_in[8];
    float* out = (float*)d_out;

    float *pq, *pk, *pv, *pctx;
    cudaGetSymbolAddress((void**)&pq,   g_q);
    cudaGetSymbolAddress((void**)&pk,   g_k);
    cudaGetSymbolAddress((void**)&pv,   g_v);
    cudaGetSymbolAddress((void**)&pctx, g_ctx);

    const int smem_attn = (3 * BQ * LDP + BKV * HDIM) * (int)sizeof(float); // ~66 KB
    cudaFuncSetAttribute(attn_kernel, cudaFuncAttributeMaxDynamicSharedMemorySize, smem_attn);

    dim3 ggrid(EMB / 128, MROWS / 128);   // (8, 64)
    gemm_bias_kernel<true><<<ggrid, 256>>>(x, w_q, b_q, pq);
    gemm_bias_kernel<true><<<ggrid, 256>>>(x, w_k, b_k, pk);
    gemm_bias_kernel<true><<<ggrid, 256>>>(x, w_v, b_v, pv);

    dim3 agrid(SEQ / BQ, BATCH * HEADS);  // (32, 64)
    attn_kernel<<<agrid, 256, smem_attn>>>(pq, pk, pv, pctx);

    gemm_bias_kernel<false><<<ggrid, 256>>>(pctx, w_o, b_o, out);
}

// round 3
// speedup vs baseline: 8.8260x; 8.8260x over previous
#include <cuda_runtime.h>
#include <cuda_bf16.h>
#include <math.h>
#include <stdint.h>

#define BATCH 4
#define SEQ   2048
#define EMB   1024
#define HEADS 16
#define HDIM  64
#define MROWS (BATCH*SEQ)          // 8192
#define SCALE 0.125f

// ---------------------------------------------------------------------------
// scratch (__device__ globals; no runtime allocation)
// ---------------------------------------------------------------------------
static __device__ __nv_bfloat16 g_xhi[(size_t)MROWS * EMB];
static __device__ __nv_bfloat16 g_xlo[(size_t)MROWS * EMB];
static __device__ __nv_bfloat16 g_wthi[(size_t)4 * EMB * EMB];
static __device__ __nv_bfloat16 g_wtlo[(size_t)4 * EMB * EMB];
static __device__ __nv_bfloat16 g_qh[(size_t)MROWS * EMB], g_ql[(size_t)MROWS * EMB];
static __device__ __nv_bfloat16 g_kh[(size_t)MROWS * EMB], g_kl[(size_t)MROWS * EMB];
static __device__ __nv_bfloat16 g_vh[(size_t)MROWS * EMB], g_vl[(size_t)MROWS * EMB];
static __device__ __nv_bfloat16 g_ch[(size_t)MROWS * EMB], g_cl[(size_t)MROWS * EMB];

// ---------------------------------------------------------------------------
// helpers
// ---------------------------------------------------------------------------
__device__ __forceinline__ uint32_t smem_u32(const void* p) {
    uint32_t a;
    asm("{ .reg .u64 t; cvta.to.shared.u64 t, %1; cvt.u32.u64 %0, t; }" : "=r"(a) : "l"(p));
    return a;
}
// SW128 swizzled byte offset for (row, bf16-elem e); rows are 128B (64 bf16)
__device__ __forceinline__ uint32_t swz(uint32_t row, uint32_t e) {
    return (row << 7) + ((((e >> 3) ^ (row & 7))) << 4) + ((e & 7) << 1);
}
#define CPA(dst, src) asm volatile("cp.async.cg.shared.global [%0], [%1], 16;" :: "r"(dst), "l"(src))
#define CPC()  asm volatile("cp.async.commit_group;" ::: "memory")
#define CPW(n) asm volatile("cp.async.wait_group %0;" :: "n"(n) : "memory")

__device__ __forceinline__ void ldsm4(uint32_t addr, uint32_t* r) {
    asm volatile("ldmatrix.sync.aligned.m8n8.x4.shared.b16 {%0,%1,%2,%3}, [%4];"
        : "=r"(r[0]), "=r"(r[1]), "=r"(r[2]), "=r"(r[3]) : "r"(addr));
}
__device__ __forceinline__ void ldsm4t(uint32_t addr, uint32_t* r) {
    asm volatile("ldmatrix.sync.aligned.m8n8.x4.trans.shared.b16 {%0,%1,%2,%3}, [%4];"
        : "=r"(r[0]), "=r"(r[1]), "=r"(r[2]), "=r"(r[3]) : "r"(addr));
}
__device__ __forceinline__ void mma16816(float* c, const uint32_t* a, uint32_t b0, uint32_t b1) {
    asm volatile("mma.sync.aligned.m16n8k16.row.col.f32.bf16.bf16.f32 "
        "{%0,%1,%2,%3}, {%4,%5,%6,%7}, {%8,%9}, {%0,%1,%2,%3};"
        : "+f"(c[0]), "+f"(c[1]), "+f"(c[2]), "+f"(c[3])
        : "r"(a[0]), "r"(a[1]), "r"(a[2]), "r"(a[3]), "r"(b0), "r"(b1));
}
// pack (v0 -> low bf16, v1 -> high bf16) and residual pack
__device__ __forceinline__ void split2(float v0, float v1, uint32_t& h, uint32_t& l) {
    asm("cvt.rn.bf16x2.f32 %0, %1, %2;" : "=r"(h) : "f"(v1), "f"(v0));
    const float h0 = __uint_as_float(h << 16);
    const float h1 = __uint_as_float(h & 0xffff0000u);
    asm("cvt.rn.bf16x2.f32 %0, %1, %2;" : "=r"(l) : "f"(v1 - h1), "f"(v0 - h0));
}

// ---------------------------------------------------------------------------
// prep kernels
// ---------------------------------------------------------------------------
__global__ void split_kernel(const float* __restrict__ in,
                             __nv_bfloat16* __restrict__ hi,
                             __nv_bfloat16* __restrict__ lo, int n4)
{
    int i = blockIdx.x * blockDim.x + threadIdx.x;
    if (i >= n4) return;
    float4 v = ((const float4*)in)[i];
    float vv[4] = { v.x, v.y, v.z, v.w };
    __align__(8) __nv_bfloat16 h[4], l[4];
#pragma unroll
    for (int j = 0; j < 4; j++) {
        h[j] = __float2bfloat16_rn(vv[j]);
        l[j] = __float2bfloat16_rn(vv[j] - __bfloat162float(h[j]));
    }
    ((uint2*)hi)[i] = *(uint2*)h;
    ((uint2*)lo)[i] = *(uint2*)l;
}

__global__ void transpose_split_kernel(const float* __restrict__ W,
                                       __nv_bfloat16* __restrict__ hi,
                                       __nv_bfloat16* __restrict__ lo)
{
    __shared__ float t[32][33];
    const int n0 = blockIdx.x * 32, k0 = blockIdx.y * 32;
    const int tx = threadIdx.x, ty = threadIdx.y;   // 32 x 8
#pragma unroll
    for (int s = 0; s < 4; s++)
        t[ty + 8 * s][tx] = W[(size_t)(k0 + ty + 8 * s) * EMB + n0 + tx];
    __syncthreads();
#pragma unroll
    for (int s = 0; s < 4; s++) {
        float v = t[tx][ty + 8 * s];
        int n = n0 + ty + 8 * s, k = k0 + tx;
        __nv_bfloat16 h = __float2bfloat16_rn(v);
        hi[(size_t)n * EMB + k] = h;
        lo[(size_t)n * EMB + k] = __float2bfloat16_rn(v - __bfloat162float(h));
    }
}

// ---------------------------------------------------------------------------
// GEMM: C[M,N] = (Ah+Al)[M,K] @ (Bh+Bl)[N,K]^T + bias  (3-mma bf16 split)
// 128x128 tile, BK=64, 8 warps (4m x 2n), warp tile 32x64, cp.async 2-stage.
// MODE 0: fp32 out [M,EMB].  MODE 1: bf16 hi/lo out in [B,H,N,D].
// ---------------------------------------------------------------------------
template <int MODE>
__global__ __launch_bounds__(256, 1)
void gemm_mma(const __nv_bfloat16* __restrict__ Ah, const __nv_bfloat16* __restrict__ Al,
              const __nv_bfloat16* __restrict__ Bh, const __nv_bfloat16* __restrict__ Bl,
              const float* __restrict__ bias, float* __restrict__ out,
              __nv_bfloat16* __restrict__ oh, __nv_bfloat16* __restrict__ ol)
{
    extern __shared__ __align__(1024) char smem[];
    const uint32_t sb = smem_u32(smem);
    const int tid = threadIdx.x, wid = tid >> 5, lane = tid & 31;
    const int gid = lane >> 2, tig = lane & 3;
    const int m0 = blockIdx.y * 128, n0 = blockIdx.x * 128;
    const int wm = wid & 3, wn = wid >> 2;

    // stage s at sb + s*65536: AH +0, AL +16384, BH +32768, BL +49152
    float acc[2][8][4];
#pragma unroll
    for (int a = 0; a < 2; a++)
#pragma unroll
        for (int b = 0; b < 8; b++)
#pragma unroll
            for (int c = 0; c < 4; c++) acc[a][b][c] = 0.f;

    const int lrow = tid >> 3, lu = tid & 7;   // base loader coords

    // prefetch stage 0
    {
        const int k0 = 0;
#pragma unroll
        for (int q = 0; q < 4; q++) {
            const int row = lrow + 32 * q;
            const uint32_t so = swz(row, lu * 8);
            const size_t ga = (size_t)(m0 + row) * EMB + k0 + lu * 8;
            const size_t gb = (size_t)(n0 + row) * EMB + k0 + lu * 8;
            CPA(sb + so,          Ah + ga);
            CPA(sb + 16384 + so,  Al + ga);
            CPA(sb + 32768 + so,  Bh + gb);
            CPA(sb + 49152 + so,  Bl + gb);
        }
        CPC();
    }

    for (int it = 0; it < 16; it++) {
        const int s = it & 1;
        if (it < 15) {
            const int k0 = (it + 1) * 64;
            const uint32_t stb = sb + (uint32_t)((s ^ 1) * 65536);
#pragma unroll
            for (int q = 0; q < 4; q++) {
                const int row = lrow + 32 * q;
                const uint32_t so = swz(row, lu * 8);
                const size_t ga = (size_t)(m0 + row) * EMB + k0 + lu * 8;
                const size_t gb = (size_t)(n0 + row) * EMB + k0 + lu * 8;
                CPA(stb + so,          Ah + ga);
                CPA(stb + 16384 + so,  Al + ga);
                CPA(stb + 32768 + so,  Bh + gb);
                CPA(stb + 49152 + so,  Bl + gb);
            }
            CPC();
            CPW(1);
        } else {
            CPW(0);
        }
        __syncthreads();

        const uint32_t baseA = sb + (uint32_t)(s * 65536);
        const uint32_t baseB = baseA + 32768;
#pragma unroll
        for (int t = 0; t < 4; t++) {
            uint32_t ah[2][4], al[2][4];
#pragma unroll
            for (int mt = 0; mt < 2; mt++) {
                const uint32_t r = wm * 32 + mt * 16 + (lane & 7) + ((lane >> 3) & 1) * 8;
                const uint32_t e = t * 16 + (lane >> 4) * 8;
                ldsm4(baseA + swz(r, e), ah[mt]);
                ldsm4(baseA + 16384 + swz(r, e), al[mt]);
            }
#pragma unroll
            for (int p = 0; p < 4; p++) {
                const uint32_t nr = wn * 64 + p * 16 + (lane & 7) + (lane >> 4) * 8;
                const uint32_t ne = t * 16 + ((lane >> 3) & 1) * 8;
                uint32_t bh[4], bl[4];
                ldsm4(baseB + swz(nr, ne), bh);
                ldsm4(baseB + 16384 + swz(nr, ne), bl);
#pragma unroll
                for (int mt = 0; mt < 2; mt++) {
                    mma16816(acc[mt][2 * p],     ah[mt], bh[0], bh[1]);
                    mma16816(acc[mt][2 * p + 1], ah[mt], bh[2], bh[3]);
                    mma16816(acc[mt][2 * p],     ah[mt], bl[0], bl[1]);
                    mma16816(acc[mt][2 * p + 1], ah[mt], bl[2], bl[3]);
                    mma16816(acc[mt][2 * p],     al[mt], bh[0], bh[1]);
                    mma16816(acc[mt][2 * p + 1], al[mt], bh[2], bh[3]);
                }
            }
        }
        __syncthreads();
    }

    // epilogue
#pragma unroll
    for (int mt = 0; mt < 2; mt++) {
        const int m = m0 + wm * 32 + mt * 16 + gid;
#pragma unroll
        for (int j = 0; j < 8; j++) {
            const int n = n0 + wn * 64 + j * 8 + tig * 2;
            const float bs0 = bias[n], bs1 = bias[n + 1];
            const float v0 = acc[mt][j][0] + bs0, v1 = acc[mt][j][1] + bs1;
            const float v2 = acc[mt][j][2] + bs0, v3 = acc[mt][j][3] + bs1;
            if (MODE == 0) {
                *(float2*)(out + (size_t)m * EMB + n)       = make_float2(v0, v1);
                *(float2*)(out + (size_t)(m + 8) * EMB + n) = make_float2(v2, v3);
            } else {
                const int h = n >> 6, d = n & 63;
                const int b = m >> 11, nn = m & 2047;
                const size_t off0 = ((((size_t)b * HEADS + h) * SEQ + nn) << 6) + d;
                const size_t off1 = off0 + (8 << 6);
                uint32_t ph, pl;
                split2(v0, v1, ph, pl);
                *(uint32_t*)(oh + off0) = ph; *(uint32_t*)(ol + off0) = pl;
                split2(v2, v3, ph, pl);
                *(uint32_t*)(oh + off1) = ph; *(uint32_t*)(ol + off1) = pl;
            }
        }
    }
}

// ---------------------------------------------------------------------------
// flash attention on mma.sync: CTA = 128 Q rows, 8 warps x 16 rows, KV tile 64
// ---------------------------------------------------------------------------
__global__ __launch_bounds__(256, 1)
void attn_mma(const __nv_bfloat16* __restrict__ qh, const __nv_bfloat16* __restrict__ ql,
              const __nv_bfloat16* __restrict__ kh, const __nv_bfloat16* __restrict__ kl,
              const __nv_bfloat16* __restrict__ vh, const __nv_bfloat16* __restrict__ vl,
              __nv_bfloat16* __restrict__ ch, __nv_bfloat16* __restrict__ cl)
{
    extern __shared__ __align__(1024) char smem[];
    const uint32_t sb = smem_u32(smem);
    const int tid = threadIdx.x, wid = tid >> 5, lane = tid & 31;
    const int gid = lane >> 2, tig = lane & 3;
    const int bh_ = blockIdx.y, qt = blockIdx.x;

    // smem: QH 0 (16K), QL 16384; stage s at 32768+s*32768: KH+0 KL+8192 VH+16384 VL+24576
    const size_t qoff = ((size_t)bh_ * SEQ + qt * 128) * HDIM;
    const size_t kvoff = (size_t)bh_ * SEQ * HDIM;

    const int lrow = tid >> 3, lu = tid & 7;

    // prefetch Q + stage 0
    {
#pragma unroll
        for (int q = 0; q < 4; q++) {
            const int row = lrow + 32 * q;
            const uint32_t so = swz(row, lu * 8);
            CPA(sb + so,         qh + qoff + (size_t)row * HDIM + lu * 8);
            CPA(sb + 16384 + so, ql + qoff + (size_t)row * HDIM + lu * 8);
        }
#pragma unroll
        for (int q = 0; q < 2; q++) {
            const int row = lrow + 32 * q;
            const uint32_t so = swz(row, lu * 8);
            const size_t g = kvoff + (size_t)row * HDIM + lu * 8;
            CPA(sb + 32768 + so,         kh + g);
            CPA(sb + 32768 + 8192 + so,  kl + g);
            CPA(sb + 32768 + 16384 + so, vh + g);
            CPA(sb + 32768 + 24576 + so, vl + g);
        }
        CPC();
    }

    float o[8][4];
#pragma unroll
    for (int j = 0; j < 8; j++)
#pragma unroll
        for (int c = 0; c < 4; c++) o[j][c] = 0.f;
    float m_lo = -INFINITY, m_hi = -INFINITY, l_lo = 0.f, l_hi = 0.f;
    uint32_t qfh[4][4], qfl[4][4];

    for (int jt = 0; jt < SEQ / 64; jt++) {
        const int s = jt & 1;
        if (jt < SEQ / 64 - 1) {
            const uint32_t stb = sb + 32768u + (uint32_t)((s ^ 1) * 32768);
            const size_t kb0 = kvoff + (size_t)(jt + 1) * 64 * HDIM;
#pragma unroll
            for (int q = 0; q < 2; q++) {
                const int row = lrow + 32 * q;
                const uint32_t so = swz(row, lu * 8);
                const size_t g = kb0 + (size_t)row * HDIM + lu * 8;
                CPA(stb + so,         kh + g);
                CPA(stb + 8192 + so,  kl + g);
                CPA(stb + 16384 + so, vh + g);
                CPA(stb + 24576 + so, vl + g);
            }
            CPC();
            CPW(1);
        } else {
            CPW(0);
        }
        __syncthreads();

        if (jt == 0) {   // Q fragments (persist in registers)
            const uint32_t r = wid * 16 + (lane & 7) + ((lane >> 3) & 1) * 8;
#pragma unroll
            for (int t = 0; t < 4; t++) {
                const uint32_t e = t * 16 + (lane >> 4) * 8;
                ldsm4(sb + swz(r, e), qfh[t]);
                ldsm4(sb + 16384 + swz(r, e), qfl[t]);
            }
        }

        // ---- S = Q K^T (3-mma split) ----
        float s_[8][4];
#pragma unroll
        for (int j = 0; j < 8; j++)
#pragma unroll
            for (int c = 0; c < 4; c++) s_[j][c] = 0.f;

        const uint32_t KB = sb + 32768u + (uint32_t)(s * 32768);
#pragma unroll
        for (int t = 0; t < 4; t++) {
#pragma unroll
            for (int p = 0; p < 4; p++) {
                const uint32_t nr = p * 16 + (lane & 7) + (lane >> 4) * 8;
                const uint32_t ne = t * 16 + ((lane >> 3) & 1) * 8;
                uint32_t kbh[4], kbl[4];
                ldsm4(KB + swz(nr, ne), kbh);
                ldsm4(KB + 8192 + swz(nr, ne), kbl);
                mma16816(s_[2 * p],     qfh[t], kbh[0], kbh[1]);
                mma16816(s_[2 * p + 1], qfh[t], kbh[2], kbh[3]);
                mma16816(s_[2 * p],     qfh[t], kbl[0], kbl[1]);
                mma16816(s_[2 * p + 1], qfh[t], kbl[2], kbl[3]);
                mma16816(s_[2 * p],     qfl[t], kbh[0], kbh[1]);
                mma16816(s_[2 * p + 1], qfl[t], kbh[2], kbh[3]);
            }
        }

        // ---- online softmax ----
        float mx0 = -INFINITY, mx1 = -INFINITY;
#pragma unroll
        for (int j = 0; j < 8; j++) {
#pragma unroll
            for (int c = 0; c < 4; c++) s_[j][c] *= SCALE;
            mx0 = fmaxf(mx0, fmaxf(s_[j][0], s_[j][1]));
            mx1 = fmaxf(mx1, fmaxf(s_[j][2], s_[j][3]));
        }
        mx0 = fmaxf(mx0, __shfl_xor_sync(0xffffffffu, mx0, 1));
        mx0 = fmaxf(mx0, __shfl_xor_sync(0xffffffffu, mx0, 2));
        mx1 = fmaxf(mx1, __shfl_xor_sync(0xffffffffu, mx1, 1));
        mx1 = fmaxf(mx1, __shfl_xor_sync(0xffffffffu, mx1, 2));
        const float mn0 = fmaxf(m_lo, mx0), mn1 = fmaxf(m_hi, mx1);
        const float cr0 = __expf(m_lo - mn0), cr1 = __expf(m_hi - mn1);
        m_lo = mn0; m_hi = mn1;
        float ps0 = 0.f, ps1 = 0.f;
#pragma unroll
        for (int j = 0; j < 8; j++) {
            s_[j][0] = __expf(s_[j][0] - mn0); ps0 += s_[j][0];
            s_[j][1] = __expf(s_[j][1] - mn0); ps0 += s_[j][1];
            s_[j][2] = __expf(s_[j][2] - mn1); ps1 += s_[j][2];
            s_[j][3] = __expf(s_[j][3] - mn1); ps1 += s_[j][3];
        }
        ps0 += __shfl_xor_sync(0xffffffffu, ps0, 1);
        ps0 += __shfl_xor_sync(0xffffffffu, ps0, 2);
        ps1 += __shfl_xor_sync(0xffffffffu, ps1, 1);
        ps1 += __shfl_xor_sync(0xffffffffu, ps1, 2);
        l_lo = l_lo * cr0 + ps0;
        l_hi = l_hi * cr1 + ps1;
#pragma unroll
        for (int j = 0; j < 8; j++) {
            o[j][0] *= cr0; o[j][1] *= cr0;
            o[j][2] *= cr1; o[j][3] *= cr1;
        }

        // ---- O += P V (3-mma split; P fragments from accumulators) ----
        const uint32_t VB = KB + 16384;
#pragma unroll
        for (int t = 0; t < 4; t++) {
            uint32_t pah[4], pal[4];
            split2(s_[2 * t][0],     s_[2 * t][1],     pah[0], pal[0]);
            split2(s_[2 * t][2],     s_[2 * t][3],     pah[1], pal[1]);
            split2(s_[2 * t + 1][0], s_[2 * t + 1][1], pah[2], pal[2]);
            split2(s_[2 * t + 1][2], s_[2 * t + 1][3], pah[3], pal[3]);
#pragma unroll
            for (int p = 0; p < 4; p++) {
                const uint32_t vr = t * 16 + (lane & 7) + ((lane >> 3) & 1) * 8;
                const uint32_t ve = p * 16 + (lane >> 4) * 8;
                uint32_t vbh[4], vbl[4];
                ldsm4t(VB + swz(vr, ve), vbh);
                ldsm4t(VB + 8192 + swz(vr, ve), vbl);
                mma16816(o[2 * p],     pah, vbh[0], vbh[1]);
                mma16816(o[2 * p + 1], pah, vbh[2], vbh[3]);
                mma16816(o[2 * p],     pah, vbl[0], vbl[1]);
                mma16816(o[2 * p + 1], pah, vbl[2], vbl[3]);
                mma16816(o[2 * p],     pal, vbh[0], vbh[1]);
                mma16816(o[2 * p + 1], pal, vbh[2], vbh[3]);
            }
        }
        __syncthreads();
    }

    // epilogue: normalize + bf16 hi/lo split into [B,N,C]
    const float inv0 = 1.f / l_lo, inv1 = 1.f / l_hi;
    const int b = bh_ >> 4, h = bh_ & 15;
    const int n_lo = qt * 128 + wid * 16 + gid;
    const size_t base0 = ((size_t)b * SEQ + n_lo) * EMB + h * HDIM;
    const size_t base1 = base0 + (size_t)8 * EMB;
#pragma unroll
    for (int j = 0; j < 8; j++) {
        const int d = j * 8 + tig * 2;
        uint32_t ph, pl;
        split2(o[j][0] * inv0, o[j][1] * inv0, ph, pl);
        *(uint32_t*)(ch + base0 + d) = ph; *(uint32_t*)(cl + base0 + d) = pl;
        split2(o[j][2] * inv1, o[j][3] * inv1, ph, pl);
        *(uint32_t*)(ch + base1 + d) = ph; *(uint32_t*)(cl + base1 + d) = pl;
    }
}

// ---------------------------------------------------------------------------
extern "C" void kernel_launch(void* const* d_in, const int* in_sizes, int n_in,
                              void* d_out, int out_size)
{
    const float* x   = (const float*)d_in[0];
    const float* w_q = (const float*)d_in[1];
    const float* b_q = (const float*)d_in[2];
    const float* w_k = (const float*)d_in[3];
    const float* b_k = (const float*)d_in[4];
    const float* w_v = (const float*)d_in[5];
    const float* b_v = (const float*)d_in[6];
    const float* w_o = (const float*)d_in[7];
    const float* b_o = (const float*)d_in[8];
    float* out = (float*)d_out;

    __nv_bfloat16 *xhi, *xlo, *wthi, *wtlo, *qh, *ql, *kh, *kl, *vh, *vl, *ch, *cl;
    cudaGetSymbolAddress((void**)&xhi,  g_xhi);
    cudaGetSymbolAddress((void**)&xlo,  g_xlo);
    cudaGetSymbolAddress((void**)&wthi, g_wthi);
    cudaGetSymbolAddress((void**)&wtlo, g_wtlo);
    cudaGetSymbolAddress((void**)&qh,   g_qh);
    cudaGetSymbolAddress((void**)&ql,   g_ql);
    cudaGetSymbolAddress((void**)&kh,   g_kh);
    cudaGetSymbolAddress((void**)&kl,   g_kl);
    cudaGetSymbolAddress((void**)&vh,   g_vh);
    cudaGetSymbolAddress((void**)&vl,   g_vl);
    cudaGetSymbolAddress((void**)&ch,   g_ch);
    cudaGetSymbolAddress((void**)&cl,   g_cl);

    const size_t WSZ = (size_t)EMB * EMB;

    split_kernel<<<(MROWS * EMB / 4 + 255) / 256, 256>>>(x, xhi, xlo, MROWS * EMB / 4);
    dim3 tgrid(32, 32), tblk(32, 8);
    transpose_split_kernel<<<tgrid, tblk>>>(w_q, wthi + 0 * WSZ, wtlo + 0 * WSZ);
    transpose_split_kernel<<<tgrid, tblk>>>(w_k, wthi + 1 * WSZ, wtlo + 1 * WSZ);
    transpose_split_kernel<<<tgrid, tblk>>>(w_v, wthi + 2 * WSZ, wtlo + 2 * WSZ);
    transpose_split_kernel<<<tgrid, tblk>>>(w_o, wthi + 3 * WSZ, wtlo + 3 * WSZ);

    const int gemm_smem = 131072;
    cudaFuncSetAttribute(gemm_mma<0>, cudaFuncAttributeMaxDynamicSharedMemorySize, gemm_smem);
    cudaFuncSetAttribute(gemm_mma<1>, cudaFuncAttributeMaxDynamicSharedMemorySize, gemm_smem);
    dim3 ggrid(EMB / 128, MROWS / 128);   // (8, 64)
    gemm_mma<1><<<ggrid, 256, gemm_smem>>>(xhi, xlo, wthi + 0 * WSZ, wtlo + 0 * WSZ, b_q, nullptr, qh, ql);
    gemm_mma<1><<<ggrid, 256, gemm_smem>>>(xhi, xlo, wthi + 1 * WSZ, wtlo + 1 * WSZ, b_k, nullptr, kh, kl);
    gemm_mma<1><<<ggrid, 256, gemm_smem>>>(xhi, xlo, wthi + 2 * WSZ, wtlo + 2 * WSZ, b_v, nullptr, vh, vl);

    const int attn_smem = 98304;
    cudaFuncSetAttribute(attn_mma, cudaFuncAttributeMaxDynamicSharedMemorySize, attn_smem);
    dim3 agrid(SEQ / 128, BATCH * HEADS);   // (16, 64)
    attn_mma<<<agrid, 256, attn_smem>>>(qh, ql, kh, kl, vh, vl, ch, cl);

    gemm_mma<0><<<ggrid, 256, gemm_smem>>>(ch, cl, wthi + 3 * WSZ, wtlo + 3 * WSZ, b_o, out, nullptr, nullptr);
}

// round 4
// speedup vs baseline: 9.4534x; 1.0711x over previous
#include <cuda_runtime.h>
#include <cuda_bf16.h>
#include <math.h>
#include <stdint.h>

#define BATCH 4
#define SEQ   2048
#define EMB   1024
#define HEADS 16
#define HDIM  64
#define MROWS (BATCH*SEQ)          // 8192
#define SCALE 0.125f
#define PLANE ((size_t)MROWS * EMB)

// ---------------------------------------------------------------------------
// scratch
// ---------------------------------------------------------------------------
static __device__ __nv_bfloat16 g_xhi[PLANE];
static __device__ __nv_bfloat16 g_xlo[PLANE];
static __device__ __nv_bfloat16 g_wthi[(size_t)4 * EMB * EMB];
static __device__ __nv_bfloat16 g_wtlo[(size_t)4 * EMB * EMB];
static __device__ __nv_bfloat16 g_qkvh[3 * PLANE];   // q,k,v hi planes [B,N,C]
static __device__ __nv_bfloat16 g_qkvl[3 * PLANE];   // q,k,v lo planes
static __device__ __nv_bfloat16 g_ch[PLANE], g_cl[PLANE];

// ---------------------------------------------------------------------------
// helpers
// ---------------------------------------------------------------------------
__device__ __forceinline__ uint32_t smem_u32(const void* p) {
    uint32_t a;
    asm("{ .reg .u64 t; cvta.to.shared.u64 t, %1; cvt.u32.u64 %0, t; }" : "=r"(a) : "l"(p));
    return a;
}
// SW128 swizzled byte offset for (row, bf16-elem e); rows are 128B (64 bf16)
__device__ __forceinline__ uint32_t swz(uint32_t row, uint32_t e) {
    return (row << 7) + ((((e >> 3) ^ (row & 7))) << 4) + ((e & 7) << 1);
}
#define CPA(dst, src) asm volatile("cp.async.cg.shared.global [%0], [%1], 16;" :: "r"(dst), "l"(src))
#define CPC()  asm volatile("cp.async.commit_group;" ::: "memory")
#define CPW(n) asm volatile("cp.async.wait_group %0;" :: "n"(n) : "memory")

__device__ __forceinline__ void ldsm4(uint32_t addr, uint32_t* r) {
    asm volatile("ldmatrix.sync.aligned.m8n8.x4.shared.b16 {%0,%1,%2,%3}, [%4];"
        : "=r"(r[0]), "=r"(r[1]), "=r"(r[2]), "=r"(r[3]) : "r"(addr));
}
__device__ __forceinline__ void ldsm4t(uint32_t addr, uint32_t* r) {
    asm volatile("ldmatrix.sync.aligned.m8n8.x4.trans.shared.b16 {%0,%1,%2,%3}, [%4];"
        : "=r"(r[0]), "=r"(r[1]), "=r"(r[2]), "=r"(r[3]) : "r"(addr));
}
__device__ __forceinline__ void mma16816(float* c, const uint32_t* a, uint32_t b0, uint32_t b1) {
    asm volatile("mma.sync.aligned.m16n8k16.row.col.f32.bf16.bf16.f32 "
        "{%0,%1,%2,%3}, {%4,%5,%6,%7}, {%8,%9}, {%0,%1,%2,%3};"
        : "+f"(c[0]), "+f"(c[1]), "+f"(c[2]), "+f"(c[3])
        : "r"(a[0]), "r"(a[1]), "r"(a[2]), "r"(a[3]), "r"(b0), "r"(b1));
}
__device__ __forceinline__ void split2(float v0, float v1, uint32_t& h, uint32_t& l) {
    asm("cvt.rn.bf16x2.f32 %0, %1, %2;" : "=r"(h) : "f"(v1), "f"(v0));
    const float h0 = __uint_as_float(h << 16);
    const float h1 = __uint_as_float(h & 0xffff0000u);
    asm("cvt.rn.bf16x2.f32 %0, %1, %2;" : "=r"(l) : "f"(v1 - h1), "f"(v0 - h0));
}

// ---------------------------------------------------------------------------
// prep kernels
// ---------------------------------------------------------------------------
__global__ void split_kernel(const float* __restrict__ in,
                             __nv_bfloat16* __restrict__ hi,
                             __nv_bfloat16* __restrict__ lo, int n4)
{
    int i = blockIdx.x * blockDim.x + threadIdx.x;
    if (i >= n4) return;
    float4 v = ((const float4*)in)[i];
    float vv[4] = { v.x, v.y, v.z, v.w };
    __align__(8) __nv_bfloat16 h[4], l[4];
#pragma unroll
    for (int j = 0; j < 4; j++) {
        h[j] = __float2bfloat16_rn(vv[j]);
        l[j] = __float2bfloat16_rn(vv[j] - __bfloat162float(h[j]));
    }
    ((uint2*)hi)[i] = *(uint2*)h;
    ((uint2*)lo)[i] = *(uint2*)l;
}

__global__ void transpose_split_kernel(const float* __restrict__ W,
                                       __nv_bfloat16* __restrict__ hi,
                                       __nv_bfloat16* __restrict__ lo)
{
    __shared__ float t[32][33];
    const int n0 = blockIdx.x * 32, k0 = blockIdx.y * 32;
    const int tx = threadIdx.x, ty = threadIdx.y;   // 32 x 8
#pragma unroll
    for (int s = 0; s < 4; s++)
        t[ty + 8 * s][tx] = W[(size_t)(k0 + ty + 8 * s) * EMB + n0 + tx];
    __syncthreads();
#pragma unroll
    for (int s = 0; s < 4; s++) {
        float v = t[tx][ty + 8 * s];
        int n = n0 + ty + 8 * s, k = k0 + tx;
        __nv_bfloat16 h = __float2bfloat16_rn(v);
        hi[(size_t)n * EMB + k] = h;
        lo[(size_t)n * EMB + k] = __float2bfloat16_rn(v - __bfloat162float(h));
    }
}

// ---------------------------------------------------------------------------
// GEMM: C[M,N] = (Ah+Al)[M,K] @ (Bh+Bl)[N,K]^T + bias  (3-mma bf16 split)
// 128x128 tile, BK=64, 8 warps (4m x 2n), cp.async 2-stage.
// MODE 0: fp32 out [M,EMB] (single z).  MODE 1: z in {0,1,2} -> q/k/v hi/lo
// planes in [B,N,C]; z==0 scaled by SCALE.
// ---------------------------------------------------------------------------
template <int MODE>
__global__ __launch_bounds__(256, 1)
void gemm_mma(const __nv_bfloat16* __restrict__ Ah, const __nv_bfloat16* __restrict__ Al,
              const __nv_bfloat16* __restrict__ Wh, const __nv_bfloat16* __restrict__ Wl,
              const float* __restrict__ bq, const float* __restrict__ bk,
              const float* __restrict__ bv,
              float* __restrict__ out,
              __nv_bfloat16* __restrict__ oh, __nv_bfloat16* __restrict__ ol)
{
    extern __shared__ __align__(1024) char smem[];
    const uint32_t sb = smem_u32(smem);
    const int tid = threadIdx.x, wid = tid >> 5, lane = tid & 31;
    const int gid = lane >> 2, tig = lane & 3;
    const int m0 = blockIdx.y * 128, n0 = blockIdx.x * 128;
    const int wm = wid & 3, wn = wid >> 2;
    const int z = blockIdx.z;

    const size_t WSZ = (size_t)EMB * EMB;
    const __nv_bfloat16* Bh = Wh + (size_t)z * WSZ;
    const __nv_bfloat16* Bl = Wl + (size_t)z * WSZ;
    const float* bias = (MODE == 0) ? bq : (z == 0 ? bq : (z == 1 ? bk : bv));
    const float scale = (MODE == 1 && z == 0) ? SCALE : 1.f;

    float acc[2][8][4];
#pragma unroll
    for (int a = 0; a < 2; a++)
#pragma unroll
        for (int b = 0; b < 8; b++)
#pragma unroll
            for (int c = 0; c < 4; c++) acc[a][b][c] = 0.f;

    const int lrow = tid >> 3, lu = tid & 7;

    // prefetch stage 0
#pragma unroll
    for (int q = 0; q < 4; q++) {
        const int row = lrow + 32 * q;
        const uint32_t so = swz(row, lu * 8);
        const size_t ga = (size_t)(m0 + row) * EMB + lu * 8;
        const size_t gb = (size_t)(n0 + row) * EMB + lu * 8;
        CPA(sb + so,          Ah + ga);
        CPA(sb + 16384 + so,  Al + ga);
        CPA(sb + 32768 + so,  Bh + gb);
        CPA(sb + 49152 + so,  Bl + gb);
    }
    CPC();

    for (int it = 0; it < 16; it++) {
        const int s = it & 1;
        if (it < 15) {
            const int k0 = (it + 1) * 64;
            const uint32_t stb = sb + (uint32_t)((s ^ 1) * 65536);
#pragma unroll
            for (int q = 0; q < 4; q++) {
                const int row = lrow + 32 * q;
                const uint32_t so = swz(row, lu * 8);
                const size_t ga = (size_t)(m0 + row) * EMB + k0 + lu * 8;
                const size_t gb = (size_t)(n0 + row) * EMB + k0 + lu * 8;
                CPA(stb + so,          Ah + ga);
                CPA(stb + 16384 + so,  Al + ga);
                CPA(stb + 32768 + so,  Bh + gb);
                CPA(stb + 49152 + so,  Bl + gb);
            }
            CPC();
            CPW(1);
        } else {
            CPW(0);
        }
        __syncthreads();

        const uint32_t baseA = sb + (uint32_t)(s * 65536);
        const uint32_t baseB = baseA + 32768;
#pragma unroll
        for (int t = 0; t < 4; t++) {
            uint32_t ah[2][4], al[2][4];
#pragma unroll
            for (int mt = 0; mt < 2; mt++) {
                const uint32_t r = wm * 32 + mt * 16 + (lane & 7) + ((lane >> 3) & 1) * 8;
                const uint32_t e = t * 16 + (lane >> 4) * 8;
                ldsm4(baseA + swz(r, e), ah[mt]);
                ldsm4(baseA + 16384 + swz(r, e), al[mt]);
            }
#pragma unroll
            for (int p = 0; p < 4; p++) {
                const uint32_t nr = wn * 64 + p * 16 + (lane & 7) + (lane >> 4) * 8;
                const uint32_t ne = t * 16 + ((lane >> 3) & 1) * 8;
                uint32_t bh[4], bl[4];
                ldsm4(baseB + swz(nr, ne), bh);
                ldsm4(baseB + 16384 + swz(nr, ne), bl);
                // distance-4 interleave over (mt, n8-half) per split term
                mma16816(acc[0][2 * p],     ah[0], bh[0], bh[1]);
                mma16816(acc[0][2 * p + 1], ah[0], bh[2], bh[3]);
                mma16816(acc[1][2 * p],     ah[1], bh[0], bh[1]);
                mma16816(acc[1][2 * p + 1], ah[1], bh[2], bh[3]);
                mma16816(acc[0][2 * p],     ah[0], bl[0], bl[1]);
                mma16816(acc[0][2 * p + 1], ah[0], bl[2], bl[3]);
                mma16816(acc[1][2 * p],     ah[1], bl[0], bl[1]);
                mma16816(acc[1][2 * p + 1], ah[1], bl[2], bl[3]);
                mma16816(acc[0][2 * p],     al[0], bh[0], bh[1]);
                mma16816(acc[0][2 * p + 1], al[0], bh[2], bh[3]);
                mma16816(acc[1][2 * p],     al[1], bh[0], bh[1]);
                mma16816(acc[1][2 * p + 1], al[1], bh[2], bh[3]);
            }
        }
        __syncthreads();
    }

    // epilogue
    __nv_bfloat16* ohz = oh + (size_t)z * PLANE;
    __nv_bfloat16* olz = ol + (size_t)z * PLANE;
#pragma unroll
    for (int mt = 0; mt < 2; mt++) {
        const int m = m0 + wm * 32 + mt * 16 + gid;
#pragma unroll
        for (int j = 0; j < 8; j++) {
            const int n = n0 + wn * 64 + j * 8 + tig * 2;
            const float bs0 = bias[n], bs1 = bias[n + 1];
            const float v0 = (acc[mt][j][0] + bs0) * scale, v1 = (acc[mt][j][1] + bs1) * scale;
            const float v2 = (acc[mt][j][2] + bs0) * scale, v3 = (acc[mt][j][3] + bs1) * scale;
            if (MODE == 0) {
                *(float2*)(out + (size_t)m * EMB + n)       = make_float2(v0, v1);
                *(float2*)(out + (size_t)(m + 8) * EMB + n) = make_float2(v2, v3);
            } else {
                const size_t off0 = (size_t)m * EMB + n;
                const size_t off1 = off0 + 8 * EMB;
                uint32_t ph, pl;
                split2(v0, v1, ph, pl);
                *(uint32_t*)(ohz + off0) = ph; *(uint32_t*)(olz + off0) = pl;
                split2(v2, v3, ph, pl);
                *(uint32_t*)(ohz + off1) = ph; *(uint32_t*)(olz + off1) = pl;
            }
        }
    }
}

// ---------------------------------------------------------------------------
// flash attention on mma.sync: CTA = 128 Q rows, 8 warps x 16 rows, KV tile 64
// Q/K/V in [B,N,C] hi/lo planes (Q pre-scaled). 2 CTAs/SM target.
// ---------------------------------------------------------------------------
__global__ __launch_bounds__(256, 2)
void attn_mma(const __nv_bfloat16* __restrict__ qh, const __nv_bfloat16* __restrict__ ql,
              const __nv_bfloat16* __restrict__ kh, const __nv_bfloat16* __restrict__ kl,
              const __nv_bfloat16* __restrict__ vh, const __nv_bfloat16* __restrict__ vl,
              __nv_bfloat16* __restrict__ ch, __nv_bfloat16* __restrict__ cl)
{
    extern __shared__ __align__(1024) char smem[];
    const uint32_t sb = smem_u32(smem);
    const int tid = threadIdx.x, wid = tid >> 5, lane = tid & 31;
    const int gid = lane >> 2, tig = lane & 3;
    const int bh_ = blockIdx.y, qt = blockIdx.x;
    const int b = bh_ >> 4, h = bh_ & 15;

    // smem: QH 0 (16K), QL 16384; stage s at 32768+s*32768: KH+0 KL+8192 VH+16384 VL+24576
    const size_t qrow0 = ((size_t)(b * SEQ + qt * 128)) * EMB + h * HDIM;
    const size_t krow0 = ((size_t)(b * SEQ)) * EMB + h * HDIM;

    const int lrow = tid >> 3, lu = tid & 7;

    // prefetch Q + stage 0
#pragma unroll
    for (int q = 0; q < 4; q++) {
        const int row = lrow + 32 * q;
        const uint32_t so = swz(row, lu * 8);
        CPA(sb + so,         qh + qrow0 + (size_t)row * EMB + lu * 8);
        CPA(sb + 16384 + so, ql + qrow0 + (size_t)row * EMB + lu * 8);
    }
#pragma unroll
    for (int q = 0; q < 2; q++) {
        const int row = lrow + 32 * q;
        const uint32_t so = swz(row, lu * 8);
        const size_t g = krow0 + (size_t)row * EMB + lu * 8;
        CPA(sb + 32768 + so,         kh + g);
        CPA(sb + 32768 + 8192 + so,  kl + g);
        CPA(sb + 32768 + 16384 + so, vh + g);
        CPA(sb + 32768 + 24576 + so, vl + g);
    }
    CPC();

    float o[8][4];
#pragma unroll
    for (int j = 0; j < 8; j++)
#pragma unroll
        for (int c = 0; c < 4; c++) o[j][c] = 0.f;
    float m_lo = -INFINITY, m_hi = -INFINITY, l_lo = 0.f, l_hi = 0.f;

    for (int jt = 0; jt < SEQ / 64; jt++) {
        const int s = jt & 1;
        if (jt < SEQ / 64 - 1) {
            const uint32_t stb = sb + 32768u + (uint32_t)((s ^ 1) * 32768);
            const size_t kb0 = krow0 + (size_t)(jt + 1) * 64 * EMB;
#pragma unroll
            for (int q = 0; q < 2; q++) {
                const int row = lrow + 32 * q;
                const uint32_t so = swz(row, lu * 8);
                const size_t g = kb0 + (size_t)row * EMB + lu * 8;
                CPA(stb + so,         kh + g);
                CPA(stb + 8192 + so,  kl + g);
                CPA(stb + 16384 + so, vh + g);
                CPA(stb + 24576 + so, vl + g);
            }
            CPC();
            CPW(1);
        } else {
            CPW(0);
        }
        __syncthreads();

        // ---- S = Q K^T (3-mma split, Q frags reloaded per t) ----
        float s_[8][4];
#pragma unroll
        for (int j = 0; j < 8; j++)
#pragma unroll
            for (int c = 0; c < 4; c++) s_[j][c] = 0.f;

        const uint32_t KB = sb + 32768u + (uint32_t)(s * 32768);
#pragma unroll
        for (int t = 0; t < 4; t++) {
            uint32_t qfh[4], qfl[4];
            {
                const uint32_t r = wid * 16 + (lane & 7) + ((lane >> 3) & 1) * 8;
                const uint32_t e = t * 16 + (lane >> 4) * 8;
                ldsm4(sb + swz(r, e), qfh);
                ldsm4(sb + 16384 + swz(r, e), qfl);
            }
#pragma unroll
            for (int pp = 0; pp < 4; pp += 2) {
                const uint32_t ne = t * 16 + ((lane >> 3) & 1) * 8;
                const uint32_t nr0 = pp * 16 + (lane & 7) + (lane >> 4) * 8;
                const uint32_t nr1 = nr0 + 16;
                uint32_t k0h[4], k0l[4], k1h[4], k1l[4];
                ldsm4(KB + swz(nr0, ne), k0h);
                ldsm4(KB + 8192 + swz(nr0, ne), k0l);
                ldsm4(KB + swz(nr1, ne), k1h);
                ldsm4(KB + 8192 + swz(nr1, ne), k1l);
                mma16816(s_[2 * pp],     qfh, k0h[0], k0h[1]);
                mma16816(s_[2 * pp + 1], qfh, k0h[2], k0h[3]);
                mma16816(s_[2 * pp + 2], qfh, k1h[0], k1h[1]);
                mma16816(s_[2 * pp + 3], qfh, k1h[2], k1h[3]);
                mma16816(s_[2 * pp],     qfh, k0l[0], k0l[1]);
                mma16816(s_[2 * pp + 1], qfh, k0l[2], k0l[3]);
                mma16816(s_[2 * pp + 2], qfh, k1l[0], k1l[1]);
                mma16816(s_[2 * pp + 3], qfh, k1l[2], k1l[3]);
                mma16816(s_[2 * pp],     qfl, k0h[0], k0h[1]);
                mma16816(s_[2 * pp + 1], qfl, k0h[2], k0h[3]);
                mma16816(s_[2 * pp + 2], qfl, k1h[0], k1h[1]);
                mma16816(s_[2 * pp + 3], qfl, k1h[2], k1h[3]);
            }
        }

        // ---- online softmax (Q pre-scaled, no mult here) ----
        float mx0 = -INFINITY, mx1 = -INFINITY;
#pragma unroll
        for (int j = 0; j < 8; j++) {
            mx0 = fmaxf(mx0, fmaxf(s_[j][0], s_[j][1]));
            mx1 = fmaxf(mx1, fmaxf(s_[j][2], s_[j][3]));
        }
        mx0 = fmaxf(mx0, __shfl_xor_sync(0xffffffffu, mx0, 1));
        mx0 = fmaxf(mx0, __shfl_xor_sync(0xffffffffu, mx0, 2));
        mx1 = fmaxf(mx1, __shfl_xor_sync(0xffffffffu, mx1, 1));
        mx1 = fmaxf(mx1, __shfl_xor_sync(0xffffffffu, mx1, 2));
        const float mn0 = fmaxf(m_lo, mx0), mn1 = fmaxf(m_hi, mx1);
        const float cr0 = __expf(m_lo - mn0), cr1 = __expf(m_hi - mn1);
        m_lo = mn0; m_hi = mn1;
        float ps0 = 0.f, ps1 = 0.f;
#pragma unroll
        for (int j = 0; j < 8; j++) {
            s_[j][0] = __expf(s_[j][0] - mn0); ps0 += s_[j][0];
            s_[j][1] = __expf(s_[j][1] - mn0); ps0 += s_[j][1];
            s_[j][2] = __expf(s_[j][2] - mn1); ps1 += s_[j][2];
            s_[j][3] = __expf(s_[j][3] - mn1); ps1 += s_[j][3];
        }
        ps0 += __shfl_xor_sync(0xffffffffu, ps0, 1);
        ps0 += __shfl_xor_sync(0xffffffffu, ps0, 2);
        ps1 += __shfl_xor_sync(0xffffffffu, ps1, 1);
        ps1 += __shfl_xor_sync(0xffffffffu, ps1, 2);
        l_lo = l_lo * cr0 + ps0;
        l_hi = l_hi * cr1 + ps1;
#pragma unroll
        for (int j = 0; j < 8; j++) {
            o[j][0] *= cr0; o[j][1] *= cr0;
            o[j][2] *= cr1; o[j][3] *= cr1;
        }

        // ---- O += P V (3-mma split) ----
        const uint32_t VB = KB + 16384;
#pragma unroll
        for (int t = 0; t < 4; t++) {
            uint32_t pah[4], pal[4];
            split2(s_[2 * t][0],     s_[2 * t][1],     pah[0], pal[0]);
            split2(s_[2 * t][2],     s_[2 * t][3],     pah[1], pal[1]);
            split2(s_[2 * t + 1][0], s_[2 * t + 1][1], pah[2], pal[2]);
            split2(s_[2 * t + 1][2], s_[2 * t + 1][3], pah[3], pal[3]);
            const uint32_t vr = t * 16 + (lane & 7) + ((lane >> 3) & 1) * 8;
#pragma unroll
            for (int pp = 0; pp < 4; pp += 2) {
                const uint32_t ve0 = pp * 16 + (lane >> 4) * 8;
                const uint32_t ve1 = ve0 + 16;
                uint32_t v0h[4], v0l[4], v1h[4], v1l[4];
                ldsm4t(VB + swz(vr, ve0), v0h);
                ldsm4t(VB + 8192 + swz(vr, ve0), v0l);
                ldsm4t(VB + swz(vr, ve1), v1h);
                ldsm4t(VB + 8192 + swz(vr, ve1), v1l);
                mma16816(o[2 * pp],     pah, v0h[0], v0h[1]);
                mma16816(o[2 * pp + 1], pah, v0h[2], v0h[3]);
                mma16816(o[2 * pp + 2], pah, v1h[0], v1h[1]);
                mma16816(o[2 * pp + 3], pah, v1h[2], v1h[3]);
                mma16816(o[2 * pp],     pah, v0l[0], v0l[1]);
                mma16816(o[2 * pp + 1], pah, v0l[2], v0l[3]);
                mma16816(o[2 * pp + 2], pah, v1l[0], v1l[1]);
                mma16816(o[2 * pp + 3], pah, v1l[2], v1l[3]);
                mma16816(o[2 * pp],     pal, v0h[0], v0h[1]);
                mma16816(o[2 * pp + 1], pal, v0h[2], v0h[3]);
                mma16816(o[2 * pp + 2], pal, v1h[0], v1h[1]);
                mma16816(o[2 * pp + 3], pal, v1h[2], v1h[3]);
            }
        }
        __syncthreads();
    }

    // epilogue: normalize + bf16 hi/lo split into [B,N,C]
    const float inv0 = 1.f / l_lo, inv1 = 1.f / l_hi;
    const int n_lo = qt * 128 + wid * 16 + gid;
    const size_t base0 = ((size_t)b * SEQ + n_lo) * EMB + h * HDIM;
    const size_t base1 = base0 + (size_t)8 * EMB;
#pragma unroll
    for (int j = 0; j < 8; j++) {
        const int d = j * 8 + tig * 2;
        uint32_t ph, pl;
        split2(o[j][0] * inv0, o[j][1] * inv0, ph, pl);
        *(uint32_t*)(ch + base0 + d) = ph; *(uint32_t*)(cl + base0 + d) = pl;
        split2(o[j][2] * inv1, o[j][3] * inv1, ph, pl);
        *(uint32_t*)(ch + base1 + d) = ph; *(uint32_t*)(cl + base1 + d) = pl;
    }
}

// ---------------------------------------------------------------------------
extern "C" void kernel_launch(void* const* d_in, const int* in_sizes, int n_in,
                              void* d_out, int out_size)
{
    const float* x   = (const float*)d_in[0];
    const float* w_q = (const float*)d_in[1];
    const float* b_q = (const float*)d_in[2];
    const float* w_k = (const float*)d_in[3];
    const float* b_k = (const float*)d_in[4];
    const float* w_v = (const float*)d_in[5];
    const float* b_v = (const float*)d_in[6];
    const float* w_o = (const float*)d_in[7];
    const float* b_o = (const float*)d_in[8];
    float* out = (float*)d_out;

    __nv_bfloat16 *xhi, *xlo, *wthi, *wtlo, *qkvh, *qkvl, *ch, *cl;
    cudaGetSymbolAddress((void**)&xhi,  g_xhi);
    cudaGetSymbolAddress((void**)&xlo,  g_xlo);
    cudaGetSymbolAddress((void**)&wthi, g_wthi);
    cudaGetSymbolAddress((void**)&wtlo, g_wtlo);
    cudaGetSymbolAddress((void**)&qkvh, g_qkvh);
    cudaGetSymbolAddress((void**)&qkvl, g_qkvl);
    cudaGetSymbolAddress((void**)&ch,   g_ch);
    cudaGetSymbolAddress((void**)&cl,   g_cl);

    const size_t WSZ = (size_t)EMB * EMB;

    dim3 tgrid(32, 32), tblk(32, 8);
    transpose_split_kernel<<<tgrid, tblk>>>(w_q, wthi + 0 * WSZ, wtlo + 0 * WSZ);
    transpose_split_kernel<<<tgrid, tblk>>>(w_k, wthi + 1 * WSZ, wtlo + 1 * WSZ);
    transpose_split_kernel<<<tgrid, tblk>>>(w_v, wthi + 2 * WSZ, wtlo + 2 * WSZ);
    transpose_split_kernel<<<tgrid, tblk>>>(w_o, wthi + 3 * WSZ, wtlo + 3 * WSZ);
    split_kernel<<<(MROWS * EMB / 4 + 255) / 256, 256>>>(x, xhi, xlo, MROWS * EMB / 4);

    const int gemm_smem = 131072;
    cudaFuncSetAttribute(gemm_mma<0>, cudaFuncAttributeMaxDynamicSharedMemorySize, gemm_smem);
    cudaFuncSetAttribute(gemm_mma<1>, cudaFuncAttributeMaxDynamicSharedMemorySize, gemm_smem);

    // fused QKV projections (z = 0,1,2), Q pre-scaled by SCALE
    dim3 ggrid3(EMB / 128, MROWS / 128, 3);   // (8, 64, 3)
    gemm_mma<1><<<ggrid3, 256, gemm_smem>>>(xhi, xlo, wthi, wtlo, b_q, b_k, b_v,
                                            nullptr, qkvh, qkvl);

    const int attn_smem = 98304;
    cudaFuncSetAttribute(attn_mma, cudaFuncAttributeMaxDynamicSharedMemorySize, attn_smem);
    dim3 agrid(SEQ / 128, BATCH * HEADS);   // (16, 64)
    attn_mma<<<agrid, 256, attn_smem>>>(qkvh, qkvl,
                                        qkvh + PLANE, qkvl + PLANE,
                                        qkvh + 2 * PLANE, qkvl + 2 * PLANE,
                                        ch, cl);

    dim3 ggrid(EMB / 128, MROWS / 128, 1);
    gemm_mma<0><<<ggrid, 256, gemm_smem>>>(ch, cl, wthi + 3 * WSZ, wtlo + 3 * WSZ,
                                           b_o, nullptr, nullptr, out, nullptr, nullptr);
}

// round 5
// speedup vs baseline: 9.5508x; 1.0103x over previous
#include <cuda_runtime.h>
#include <cuda_bf16.h>
#include <math.h>
#include <stdint.h>

#define BATCH 4
#define SEQ   2048
#define EMB   1024
#define HEADS 16
#define HDIM  64
#define MROWS (BATCH*SEQ)          // 8192
#define SCALE 0.125f
#define PLANE ((size_t)MROWS * EMB)

// ---------------------------------------------------------------------------
// scratch
// ---------------------------------------------------------------------------
static __device__ __nv_bfloat16 g_xhi[PLANE];
static __device__ __nv_bfloat16 g_xlo[PLANE];
static __device__ __nv_bfloat16 g_wthi[(size_t)4 * EMB * EMB];
static __device__ __nv_bfloat16 g_wtlo[(size_t)4 * EMB * EMB];
static __device__ __nv_bfloat16 g_qkvh[3 * PLANE];   // q,k,v hi planes [B,N,C]
static __device__ __nv_bfloat16 g_qkvl[3 * PLANE];   // q,k,v lo planes
static __device__ __nv_bfloat16 g_ch[PLANE], g_cl[PLANE];
static __device__ int g_tile_ctr;                    // attention work-steal counter

// ---------------------------------------------------------------------------
// helpers
// ---------------------------------------------------------------------------
__device__ __forceinline__ uint32_t smem_u32(const void* p) {
    uint32_t a;
    asm("{ .reg .u64 t; cvta.to.shared.u64 t, %1; cvt.u32.u64 %0, t; }" : "=r"(a) : "l"(p));
    return a;
}
// SW128 swizzled byte offset for (row, bf16-elem e); rows are 128B (64 bf16)
__device__ __forceinline__ uint32_t swz(uint32_t row, uint32_t e) {
    return (row << 7) + ((((e >> 3) ^ (row & 7))) << 4) + ((e & 7) << 1);
}
#define CPA(dst, src) asm volatile("cp.async.cg.shared.global [%0], [%1], 16;" :: "r"(dst), "l"(src))
#define CPC()  asm volatile("cp.async.commit_group;" ::: "memory")
#define CPW(n) asm volatile("cp.async.wait_group %0;" :: "n"(n) : "memory")

__device__ __forceinline__ void ldsm4(uint32_t addr, uint32_t* r) {
    asm volatile("ldmatrix.sync.aligned.m8n8.x4.shared.b16 {%0,%1,%2,%3}, [%4];"
        : "=r"(r[0]), "=r"(r[1]), "=r"(r[2]), "=r"(r[3]) : "r"(addr));
}
__device__ __forceinline__ void ldsm4t(uint32_t addr, uint32_t* r) {
    asm volatile("ldmatrix.sync.aligned.m8n8.x4.trans.shared.b16 {%0,%1,%2,%3}, [%4];"
        : "=r"(r[0]), "=r"(r[1]), "=r"(r[2]), "=r"(r[3]) : "r"(addr));
}
__device__ __forceinline__ void mma16816(float* c, const uint32_t* a, uint32_t b0, uint32_t b1) {
    asm volatile("mma.sync.aligned.m16n8k16.row.col.f32.bf16.bf16.f32 "
        "{%0,%1,%2,%3}, {%4,%5,%6,%7}, {%8,%9}, {%0,%1,%2,%3};"
        : "+f"(c[0]), "+f"(c[1]), "+f"(c[2]), "+f"(c[3])
        : "r"(a[0]), "r"(a[1]), "r"(a[2]), "r"(a[3]), "r"(b0), "r"(b1));
}
__device__ __forceinline__ void split2(float v0, float v1, uint32_t& h, uint32_t& l) {
    asm("cvt.rn.bf16x2.f32 %0, %1, %2;" : "=r"(h) : "f"(v1), "f"(v0));
    const float h0 = __uint_as_float(h << 16);
    const float h1 = __uint_as_float(h & 0xffff0000u);
    asm("cvt.rn.bf16x2.f32 %0, %1, %2;" : "=r"(l) : "f"(v1 - h1), "f"(v0 - h0));
}

// ---------------------------------------------------------------------------
// prep kernels
// ---------------------------------------------------------------------------
__global__ void split_kernel(const float* __restrict__ in,
                             __nv_bfloat16* __restrict__ hi,
                             __nv_bfloat16* __restrict__ lo, int n4)
{
    if (blockIdx.x == 0 && threadIdx.x == 0) g_tile_ctr = 0;   // reset steal counter
    int i = blockIdx.x * blockDim.x + threadIdx.x;
    if (i >= n4) return;
    float4 v = ((const float4*)in)[i];
    float vv[4] = { v.x, v.y, v.z, v.w };
    __align__(8) __nv_bfloat16 h[4], l[4];
#pragma unroll
    for (int j = 0; j < 4; j++) {
        h[j] = __float2bfloat16_rn(vv[j]);
        l[j] = __float2bfloat16_rn(vv[j] - __bfloat162float(h[j]));
    }
    ((uint2*)hi)[i] = *(uint2*)h;
    ((uint2*)lo)[i] = *(uint2*)l;
}

// all 4 weight transposes in one launch (z selects weight)
__global__ void transpose_split4(const float* __restrict__ w0, const float* __restrict__ w1,
                                 const float* __restrict__ w2, const float* __restrict__ w3,
                                 __nv_bfloat16* __restrict__ hi, __nv_bfloat16* __restrict__ lo)
{
    __shared__ float t[32][33];
    const int z = blockIdx.z;
    const float* W = (z == 0) ? w0 : (z == 1) ? w1 : (z == 2) ? w2 : w3;
    const size_t WSZ = (size_t)EMB * EMB;
    hi += (size_t)z * WSZ;
    lo += (size_t)z * WSZ;
    const int n0 = blockIdx.x * 32, k0 = blockIdx.y * 32;
    const int tx = threadIdx.x, ty = threadIdx.y;   // 32 x 8
#pragma unroll
    for (int s = 0; s < 4; s++)
        t[ty + 8 * s][tx] = W[(size_t)(k0 + ty + 8 * s) * EMB + n0 + tx];
    __syncthreads();
#pragma unroll
    for (int s = 0; s < 4; s++) {
        float v = t[tx][ty + 8 * s];
        int n = n0 + ty + 8 * s, k = k0 + tx;
        __nv_bfloat16 h = __float2bfloat16_rn(v);
        hi[(size_t)n * EMB + k] = h;
        lo[(size_t)n * EMB + k] = __float2bfloat16_rn(v - __bfloat162float(h));
    }
}

// ---------------------------------------------------------------------------
// GEMM prefetch: one 64KB stage = AH/AL/BH/BL 128x64 bf16 tiles (SW128)
// ---------------------------------------------------------------------------
__device__ __forceinline__ void gemm_prefetch(uint32_t stb,
    const __nv_bfloat16* Ah, const __nv_bfloat16* Al,
    const __nv_bfloat16* Bh, const __nv_bfloat16* Bl,
    int m0, int n0, int k0, int lrow, int lu)
{
#pragma unroll
    for (int q = 0; q < 4; q++) {
        const int row = lrow + 32 * q;
        const uint32_t so = swz(row, lu * 8);
        const size_t ga = (size_t)(m0 + row) * EMB + k0 + lu * 8;
        const size_t gb = (size_t)(n0 + row) * EMB + k0 + lu * 8;
        CPA(stb + so,          Ah + ga);
        CPA(stb + 16384 + so,  Al + ga);
        CPA(stb + 32768 + so,  Bh + gb);
        CPA(stb + 49152 + so,  Bl + gb);
    }
}

// ---------------------------------------------------------------------------
// GEMM: C[M,N] = (Ah+Al)[M,K] @ (Bh+Bl)[N,K]^T + bias  (3-mma bf16 split)
// 128x128 tile, BK=64, 8 warps (4m x 2n), cp.async 2-stage, ONE sync/iter.
// MODE 0: fp32 out [M,EMB].  MODE 1: z in {0,1,2} -> q/k/v hi/lo planes
// in [B,N,C]; z==0 scaled by SCALE.
// ---------------------------------------------------------------------------
template <int MODE>
__global__ __launch_bounds__(256, 1)
void gemm_mma(const __nv_bfloat16* __restrict__ Ah, const __nv_bfloat16* __restrict__ Al,
              const __nv_bfloat16* __restrict__ Wh, const __nv_bfloat16* __restrict__ Wl,
              const float* __restrict__ bq, const float* __restrict__ bk,
              const float* __restrict__ bv,
              float* __restrict__ out,
              __nv_bfloat16* __restrict__ oh, __nv_bfloat16* __restrict__ ol)
{
    extern __shared__ __align__(1024) char smem[];
    const uint32_t sb = smem_u32(smem);
    const int tid = threadIdx.x, wid = tid >> 5, lane = tid & 31;
    const int gid = lane >> 2, tig = lane & 3;
    const int m0 = blockIdx.y * 128, n0 = blockIdx.x * 128;
    const int wm = wid & 3, wn = wid >> 2;
    const int z = blockIdx.z;

    const size_t WSZ = (size_t)EMB * EMB;
    const __nv_bfloat16* Bh = Wh + (size_t)z * WSZ;
    const __nv_bfloat16* Bl = Wl + (size_t)z * WSZ;
    const float* bias = (MODE == 0) ? bq : (z == 0 ? bq : (z == 1 ? bk : bv));
    const float scale = (MODE == 1 && z == 0) ? SCALE : 1.f;

    float acc[2][8][4];
#pragma unroll
    for (int a = 0; a < 2; a++)
#pragma unroll
        for (int b = 0; b < 8; b++)
#pragma unroll
            for (int c = 0; c < 4; c++) acc[a][b][c] = 0.f;

    const int lrow = tid >> 3, lu = tid & 7;

    gemm_prefetch(sb, Ah, Al, Bh, Bl, m0, n0, 0, lrow, lu);
    CPC();

    for (int it = 0; it < 16; it++) {
        const int s = it & 1;
        CPW(0);
        __syncthreads();   // stage s data ready + all warps past compute(it-1)
        if (it < 15) {
            gemm_prefetch(sb + (uint32_t)((s ^ 1) * 65536), Ah, Al, Bh, Bl,
                          m0, n0, (it + 1) * 64, lrow, lu);
            CPC();
        }

        const uint32_t baseA = sb + (uint32_t)(s * 65536);
        const uint32_t baseB = baseA + 32768;
#pragma unroll
        for (int t = 0; t < 4; t++) {
            uint32_t ah[2][4], al[2][4];
#pragma unroll
            for (int mt = 0; mt < 2; mt++) {
                const uint32_t r = wm * 32 + mt * 16 + (lane & 7) + ((lane >> 3) & 1) * 8;
                const uint32_t e = t * 16 + (lane >> 4) * 8;
                ldsm4(baseA + swz(r, e), ah[mt]);
                ldsm4(baseA + 16384 + swz(r, e), al[mt]);
            }
#pragma unroll
            for (int p = 0; p < 4; p++) {
                const uint32_t nr = wn * 64 + p * 16 + (lane & 7) + (lane >> 4) * 8;
                const uint32_t ne = t * 16 + ((lane >> 3) & 1) * 8;
                uint32_t bh[4], bl[4];
                ldsm4(baseB + swz(nr, ne), bh);
                ldsm4(baseB + 16384 + swz(nr, ne), bl);
                mma16816(acc[0][2 * p],     ah[0], bh[0], bh[1]);
                mma16816(acc[0][2 * p + 1], ah[0], bh[2], bh[3]);
                mma16816(acc[1][2 * p],     ah[1], bh[0], bh[1]);
                mma16816(acc[1][2 * p + 1], ah[1], bh[2], bh[3]);
                mma16816(acc[0][2 * p],     ah[0], bl[0], bl[1]);
                mma16816(acc[0][2 * p + 1], ah[0], bl[2], bl[3]);
                mma16816(acc[1][2 * p],     ah[1], bl[0], bl[1]);
                mma16816(acc[1][2 * p + 1], ah[1], bl[2], bl[3]);
                mma16816(acc[0][2 * p],     al[0], bh[0], bh[1]);
                mma16816(acc[0][2 * p + 1], al[0], bh[2], bh[3]);
                mma16816(acc[1][2 * p],     al[1], bh[0], bh[1]);
                mma16816(acc[1][2 * p + 1], al[1], bh[2], bh[3]);
            }
        }
        // no trailing sync: next write to stage s is guarded by the top sync of it+2
    }

    // epilogue
    __nv_bfloat16* ohz = oh + (size_t)z * PLANE;
    __nv_bfloat16* olz = ol + (size_t)z * PLANE;
#pragma unroll
    for (int mt = 0; mt < 2; mt++) {
        const int m = m0 + wm * 32 + mt * 16 + gid;
#pragma unroll
        for (int j = 0; j < 8; j++) {
            const int n = n0 + wn * 64 + j * 8 + tig * 2;
            const float bs0 = bias[n], bs1 = bias[n + 1];
            const float v0 = (acc[mt][j][0] + bs0) * scale, v1 = (acc[mt][j][1] + bs1) * scale;
            const float v2 = (acc[mt][j][2] + bs0) * scale, v3 = (acc[mt][j][3] + bs1) * scale;
            if (MODE == 0) {
                *(float2*)(out + (size_t)m * EMB + n)       = make_float2(v0, v1);
                *(float2*)(out + (size_t)(m + 8) * EMB + n) = make_float2(v2, v3);
            } else {
                const size_t off0 = (size_t)m * EMB + n;
                const size_t off1 = off0 + 8 * EMB;
                uint32_t ph, pl;
                split2(v0, v1, ph, pl);
                *(uint32_t*)(ohz + off0) = ph; *(uint32_t*)(olz + off0) = pl;
                split2(v2, v3, ph, pl);
                *(uint32_t*)(ohz + off1) = ph; *(uint32_t*)(olz + off1) = pl;
            }
        }
    }
}

// ---------------------------------------------------------------------------
// flash attention, persistent work-stealing: tile = (bh, qt), 1024 tiles.
// CTA = 128 Q rows, 8 warps x 16 rows, KV tile 64, ONE sync per KV iter.
// ---------------------------------------------------------------------------
#define ATTN_TILES (BATCH * HEADS * (SEQ / 128))   // 1024

__global__ __launch_bounds__(256, 2)
void attn_mma(const __nv_bfloat16* __restrict__ qh, const __nv_bfloat16* __restrict__ ql,
              const __nv_bfloat16* __restrict__ kh, const __nv_bfloat16* __restrict__ kl,
              const __nv_bfloat16* __restrict__ vh, const __nv_bfloat16* __restrict__ vl,
              __nv_bfloat16* __restrict__ ch, __nv_bfloat16* __restrict__ cl)
{
    extern __shared__ __align__(1024) char smem[];
    const uint32_t sb = smem_u32(smem);
    const int tid = threadIdx.x, wid = tid >> 5, lane = tid & 31;
    const int gid = lane >> 2, tig = lane & 3;
    const int lrow = tid >> 3, lu = tid & 7;

    __shared__ int s_tile;

    for (;;) {
        if (tid == 0) s_tile = atomicAdd(&g_tile_ctr, 1);
        __syncthreads();            // publish tile + cross-tile smem hazard barrier
        const int tile = s_tile;
        if (tile >= ATTN_TILES) break;

        const int qt = tile & 15, bh_ = tile >> 4;
        const int b = bh_ >> 4, h = bh_ & 15;
        const size_t qrow0 = ((size_t)(b * SEQ + qt * 128)) * EMB + h * HDIM;
        const size_t krow0 = ((size_t)(b * SEQ)) * EMB + h * HDIM;

        // prologue: Q (32KB) + KV stage 0 (32KB) in one group
#pragma unroll
        for (int q = 0; q < 4; q++) {
            const int row = lrow + 32 * q;
            const uint32_t so = swz(row, lu * 8);
            CPA(sb + so,         qh + qrow0 + (size_t)row * EMB + lu * 8);
            CPA(sb + 16384 + so, ql + qrow0 + (size_t)row * EMB + lu * 8);
        }
#pragma unroll
        for (int q = 0; q < 2; q++) {
            const int row = lrow + 32 * q;
            const uint32_t so = swz(row, lu * 8);
            const size_t g = krow0 + (size_t)row * EMB + lu * 8;
            CPA(sb + 32768 + so,         kh + g);
            CPA(sb + 32768 + 8192 + so,  kl + g);
            CPA(sb + 32768 + 16384 + so, vh + g);
            CPA(sb + 32768 + 24576 + so, vl + g);
        }
        CPC();

        float o[8][4];
#pragma unroll
        for (int j = 0; j < 8; j++)
#pragma unroll
            for (int c = 0; c < 4; c++) o[j][c] = 0.f;
        float m_lo = -INFINITY, m_hi = -INFINITY, l_lo = 0.f, l_hi = 0.f;

        for (int jt = 0; jt < SEQ / 64; jt++) {
            const int s = jt & 1;
            CPW(0);
            __syncthreads();   // stage s ready + all warps past compute(jt-1)
            if (jt < SEQ / 64 - 1) {
                const uint32_t stb = sb + 32768u + (uint32_t)((s ^ 1) * 32768);
                const size_t kb0 = krow0 + (size_t)(jt + 1) * 64 * EMB;
#pragma unroll
                for (int q = 0; q < 2; q++) {
                    const int row = lrow + 32 * q;
                    const uint32_t so = swz(row, lu * 8);
                    const size_t g = kb0 + (size_t)row * EMB + lu * 8;
                    CPA(stb + so,         kh + g);
                    CPA(stb + 8192 + so,  kl + g);
                    CPA(stb + 16384 + so, vh + g);
                    CPA(stb + 24576 + so, vl + g);
                }
                CPC();
            }

            // ---- S = Q K^T (3-mma split) ----
            float s_[8][4];
#pragma unroll
            for (int j = 0; j < 8; j++)
#pragma unroll
                for (int c = 0; c < 4; c++) s_[j][c] = 0.f;

            const uint32_t KB = sb + 32768u + (uint32_t)(s * 32768);
#pragma unroll
            for (int t = 0; t < 4; t++) {
                uint32_t qfh[4], qfl[4];
                {
                    const uint32_t r = wid * 16 + (lane & 7) + ((lane >> 3) & 1) * 8;
                    const uint32_t e = t * 16 + (lane >> 4) * 8;
                    ldsm4(sb + swz(r, e), qfh);
                    ldsm4(sb + 16384 + swz(r, e), qfl);
                }
#pragma unroll
                for (int pp = 0; pp < 4; pp += 2) {
                    const uint32_t ne = t * 16 + ((lane >> 3) & 1) * 8;
                    const uint32_t nr0 = pp * 16 + (lane & 7) + (lane >> 4) * 8;
                    const uint32_t nr1 = nr0 + 16;
                    uint32_t k0h[4], k0l[4], k1h[4], k1l[4];
                    ldsm4(KB + swz(nr0, ne), k0h);
                    ldsm4(KB + 8192 + swz(nr0, ne), k0l);
                    ldsm4(KB + swz(nr1, ne), k1h);
                    ldsm4(KB + 8192 + swz(nr1, ne), k1l);
                    mma16816(s_[2 * pp],     qfh, k0h[0], k0h[1]);
                    mma16816(s_[2 * pp + 1], qfh, k0h[2], k0h[3]);
                    mma16816(s_[2 * pp + 2], qfh, k1h[0], k1h[1]);
                    mma16816(s_[2 * pp + 3], qfh, k1h[2], k1h[3]);
                    mma16816(s_[2 * pp],     qfh, k0l[0], k0l[1]);
                    mma16816(s_[2 * pp + 1], qfh, k0l[2], k0l[3]);
                    mma16816(s_[2 * pp + 2], qfh, k1l[0], k1l[1]);
                    mma16816(s_[2 * pp + 3], qfh, k1l[2], k1l[3]);
                    mma16816(s_[2 * pp],     qfl, k0h[0], k0h[1]);
                    mma16816(s_[2 * pp + 1], qfl, k0h[2], k0h[3]);
                    mma16816(s_[2 * pp + 2], qfl, k1h[0], k1h[1]);
                    mma16816(s_[2 * pp + 3], qfl, k1h[2], k1h[3]);
                }
            }

            // ---- online softmax (Q pre-scaled) ----
            float mx0 = -INFINITY, mx1 = -INFINITY;
#pragma unroll
            for (int j = 0; j < 8; j++) {
                mx0 = fmaxf(mx0, fmaxf(s_[j][0], s_[j][1]));
                mx1 = fmaxf(mx1, fmaxf(s_[j][2], s_[j][3]));
            }
            mx0 = fmaxf(mx0, __shfl_xor_sync(0xffffffffu, mx0, 1));
            mx0 = fmaxf(mx0, __shfl_xor_sync(0xffffffffu, mx0, 2));
            mx1 = fmaxf(mx1, __shfl_xor_sync(0xffffffffu, mx1, 1));
            mx1 = fmaxf(mx1, __shfl_xor_sync(0xffffffffu, mx1, 2));
            const float mn0 = fmaxf(m_lo, mx0), mn1 = fmaxf(m_hi, mx1);
            const float cr0 = __expf(m_lo - mn0), cr1 = __expf(m_hi - mn1);
            m_lo = mn0; m_hi = mn1;
            float ps0 = 0.f, ps1 = 0.f;
#pragma unroll
            for (int j = 0; j < 8; j++) {
                s_[j][0] = __expf(s_[j][0] - mn0); ps0 += s_[j][0];
                s_[j][1] = __expf(s_[j][1] - mn0); ps0 += s_[j][1];
                s_[j][2] = __expf(s_[j][2] - mn1); ps1 += s_[j][2];
                s_[j][3] = __expf(s_[j][3] - mn1); ps1 += s_[j][3];
            }
            ps0 += __shfl_xor_sync(0xffffffffu, ps0, 1);
            ps0 += __shfl_xor_sync(0xffffffffu, ps0, 2);
            ps1 += __shfl_xor_sync(0xffffffffu, ps1, 1);
            ps1 += __shfl_xor_sync(0xffffffffu, ps1, 2);
            l_lo = l_lo * cr0 + ps0;
            l_hi = l_hi * cr1 + ps1;
#pragma unroll
            for (int j = 0; j < 8; j++) {
                o[j][0] *= cr0; o[j][1] *= cr0;
                o[j][2] *= cr1; o[j][3] *= cr1;
            }

            // ---- O += P V (3-mma split) ----
            const uint32_t VB = KB + 16384;
#pragma unroll
            for (int t = 0; t < 4; t++) {
                uint32_t pah[4], pal[4];
                split2(s_[2 * t][0],     s_[2 * t][1],     pah[0], pal[0]);
                split2(s_[2 * t][2],     s_[2 * t][3],     pah[1], pal[1]);
                split2(s_[2 * t + 1][0], s_[2 * t + 1][1], pah[2], pal[2]);
                split2(s_[2 * t + 1][2], s_[2 * t + 1][3], pah[3], pal[3]);
                const uint32_t vr = t * 16 + (lane & 7) + ((lane >> 3) & 1) * 8;
#pragma unroll
                for (int pp = 0; pp < 4; pp += 2) {
                    const uint32_t ve0 = pp * 16 + (lane >> 4) * 8;
                    const uint32_t ve1 = ve0 + 16;
                    uint32_t v0h[4], v0l[4], v1h[4], v1l[4];
                    ldsm4t(VB + swz(vr, ve0), v0h);
                    ldsm4t(VB + 8192 + swz(vr, ve0), v0l);
                    ldsm4t(VB + swz(vr, ve1), v1h);
                    ldsm4t(VB + 8192 + swz(vr, ve1), v1l);
                    mma16816(o[2 * pp],     pah, v0h[0], v0h[1]);
                    mma16816(o[2 * pp + 1], pah, v0h[2], v0h[3]);
                    mma16816(o[2 * pp + 2], pah, v1h[0], v1h[1]);
                    mma16816(o[2 * pp + 3], pah, v1h[2], v1h[3]);
                    mma16816(o[2 * pp],     pah, v0l[0], v0l[1]);
                    mma16816(o[2 * pp + 1], pah, v0l[2], v0l[3]);
                    mma16816(o[2 * pp + 2], pah, v1l[0], v1l[1]);
                    mma16816(o[2 * pp + 3], pah, v1l[2], v1l[3]);
                    mma16816(o[2 * pp],     pal, v0h[0], v0h[1]);
                    mma16816(o[2 * pp + 1], pal, v0h[2], v0h[3]);
                    mma16816(o[2 * pp + 2], pal, v1h[0], v1h[1]);
                    mma16816(o[2 * pp + 3], pal, v1h[2], v1h[3]);
                }
            }
            // no trailing sync (next stage-s write guarded by top sync of jt+2 / tile loop)
        }

        // epilogue: normalize + bf16 hi/lo split into [B,N,C]
        const float inv0 = 1.f / l_lo, inv1 = 1.f / l_hi;
        const int n_lo = qt * 128 + wid * 16 + gid;
        const size_t base0 = ((size_t)b * SEQ + n_lo) * EMB + h * HDIM;
        const size_t base1 = base0 + (size_t)8 * EMB;
#pragma unroll
        for (int j = 0; j < 8; j++) {
            const int d = j * 8 + tig * 2;
            uint32_t ph, pl;
            split2(o[j][0] * inv0, o[j][1] * inv0, ph, pl);
            *(uint32_t*)(ch + base0 + d) = ph; *(uint32_t*)(cl + base0 + d) = pl;
            split2(o[j][2] * inv1, o[j][3] * inv1, ph, pl);
            *(uint32_t*)(ch + base1 + d) = ph; *(uint32_t*)(cl + base1 + d) = pl;
        }
    }
}

// ---------------------------------------------------------------------------
extern "C" void kernel_launch(void* const* d_in, const int* in_sizes, int n_in,
                              void* d_out, int out_size)
{
    const float* x   = (const float*)d_in[0];
    const float* w_q = (const float*)d_in[1];
    const float* b_q = (const float*)d_in[2];
    const float* w_k = (const float*)d_in[3];
    const float* b_k = (const float*)d_in[4];
    const float* w_v = (const float*)d_in[5];
    const float* b_v = (const float*)d_in[6];
    const float* w_o = (const float*)d_in[7];
    const float* b_o = (const float*)d_in[8];
    float* out = (float*)d_out;

    __nv_bfloat16 *xhi, *xlo, *wthi, *wtlo, *qkvh, *qkvl, *ch, *cl;
    cudaGetSymbolAddress((void**)&xhi,  g_xhi);
    cudaGetSymbolAddress((void**)&xlo,  g_xlo);
    cudaGetSymbolAddress((void**)&wthi, g_wthi);
    cudaGetSymbolAddress((void**)&wtlo, g_wtlo);
    cudaGetSymbolAddress((void**)&qkvh, g_qkvh);
    cudaGetSymbolAddress((void**)&qkvl, g_qkvl);
    cudaGetSymbolAddress((void**)&ch,   g_ch);
    cudaGetSymbolAddress((void**)&cl,   g_cl);

    static int nsm = 0;
    if (nsm == 0) {
        int dev = 0;
        cudaGetDevice(&dev);
        cudaDeviceGetAttribute(&nsm, cudaDevAttrMultiProcessorCount, dev);
        if (nsm <= 0) nsm = 148;
    }

    const size_t WSZ = (size_t)EMB * EMB;

    dim3 tgrid(32, 32, 4), tblk(32, 8);
    transpose_split4<<<tgrid, tblk>>>(w_q, w_k, w_v, w_o, wthi, wtlo);
    split_kernel<<<(MROWS * EMB / 4 + 255) / 256, 256>>>(x, xhi, xlo, MROWS * EMB / 4);

    const int gemm_smem = 131072;
    cudaFuncSetAttribute(gemm_mma<0>, cudaFuncAttributeMaxDynamicSharedMemorySize, gemm_smem);
    cudaFuncSetAttribute(gemm_mma<1>, cudaFuncAttributeMaxDynamicSharedMemorySize, gemm_smem);

    // fused QKV projections (z = 0,1,2), Q pre-scaled by SCALE
    dim3 ggrid3(EMB / 128, MROWS / 128, 3);   // (8, 64, 3)
    gemm_mma<1><<<ggrid3, 256, gemm_smem>>>(xhi, xlo, wthi, wtlo, b_q, b_k, b_v,
                                            nullptr, qkvh, qkvl);

    const int attn_smem = 98304;
    cudaFuncSetAttribute(attn_mma, cudaFuncAttributeMaxDynamicSharedMemorySize, attn_smem);
    int agrid = 2 * nsm;
    if (agrid > ATTN_TILES) agrid = ATTN_TILES;
    attn_mma<<<agrid, 256, attn_smem>>>(qkvh, qkvl,
                                        qkvh + PLANE, qkvl + PLANE,
                                        qkvh + 2 * PLANE, qkvl + 2 * PLANE,
                                        ch, cl);

    dim3 ggrid(EMB / 128, MROWS / 128, 1);
    gemm_mma<0><<<ggrid, 256, gemm_smem>>>(ch, cl, wthi + 3 * WSZ, wtlo + 3 * WSZ,
                                           b_o, nullptr, nullptr, out, nullptr, nullptr);
}